// round 2
// baseline (speedup 1.0000x reference)
#include <cuda_runtime.h>
#include <math.h>
#include <stdint.h>

// ---------------------------------------------------------------------------
// Problem constants
//   N = 4096, DIM_IN = 256, DIM_H = 128, DIM_OUT = 128
// Pipeline:
//   Xs = relu((A_s@X_s)@W1); Xs = relu((A_s@Xs)@W2)   (same for t)
//   S  = exp((Xs@W3)@Xt^T)
//   out_s = (S@Xs)@W4 ; out_t = (S@Xt)@W4
// Output layout (flattened tuple): [out_s (4096*128) | out_t (4096*128) | S (4096*4096)]
// ---------------------------------------------------------------------------

#define GN    4096
#define DIN   256
#define DH    128

// Scratch (static device allocations — allowed per harness rules)
__device__ float g_split[4u * 4096u * 256u];   // split-K partials (max 4M floats)
__device__ float g_bufAX[4096 * 256];          // A@X intermediate
__device__ float g_bufH [4096 * 128];          // hidden layer-1 output
__device__ float g_Xs   [4096 * 128];
__device__ float g_Xt   [4096 * 128];
__device__ float g_Q    [4096 * 128];          // Xs @ W3
__device__ float g_Ps   [4096 * 128];          // S @ Xs
__device__ float g_Pt   [4096 * 128];          // S @ Xt

// ---------------------------------------------------------------------------
// Generic register-tiled fp32 GEMM.
//   C[M,N] = A[M,K] @ B            (TRANSB=false: B is [K,N] row-major, ldb = row stride)
//                                  (TRANSB=true : B is [N,K] row-major -> C = A @ B^T)
// Assumes M % BM == 0, N % BN == 0, kChunk % BK == 0 (true for all shapes here).
// gridDim.z > 1 => split-K: block z computes K range [z*kChunk, (z+1)*kChunk)
// and writes a raw partial to C + z*M*N (epi must be 0 in that case).
// epi: 0 = none, 1 = relu, 2 = exp
// ---------------------------------------------------------------------------
template <int BM, int BN, int BK, int TM, int TN, bool TRANSB>
__global__ void __launch_bounds__((BM * BN) / (TM * TN), 512 / ((BM * BN) / (TM * TN)))
gemm_kernel(const float* __restrict__ A, const float* __restrict__ B,
            float* __restrict__ C,
            int M, int N, int K, int lda, int ldb, int ldc,
            int kChunk, int epi)
{
    constexpr int THREADS = (BM * BN) / (TM * TN);
    constexpr int KV      = BK / 4;                  // float4 chunks along K
    constexpr int A_LOADS = (BM * KV) / THREADS;
    constexpr int B_LOADS = (BN * KV) / THREADS;

    __shared__ float As[BK][BM];
    __shared__ float Bs[BK][BN];

    const int tid    = threadIdx.x;
    const int trow   = (tid / (BN / TN)) * TM;
    const int tcol   = (tid % (BN / TN)) * TN;
    const int mBlock = blockIdx.y * BM;
    const int nBlock = blockIdx.x * BN;
    const int k0     = blockIdx.z * kChunk;

    if (gridDim.z > 1)
        C += (size_t)blockIdx.z * (size_t)M * (size_t)N;

    float4 pa[A_LOADS], pb[B_LOADS];

    float acc[TM][TN];
#pragma unroll
    for (int i = 0; i < TM; i++)
#pragma unroll
        for (int j = 0; j < TN; j++) acc[i][j] = 0.f;

    auto loadTiles = [&](int kt) {
#pragma unroll
        for (int i = 0; i < A_LOADS; i++) {
            int idx = tid + i * THREADS;
            int r   = idx / KV;
            int kc  = (idx % KV) * 4;
            pa[i] = *reinterpret_cast<const float4*>(
                        &A[(size_t)(mBlock + r) * lda + kt + kc]);
        }
#pragma unroll
        for (int i = 0; i < B_LOADS; i++) {
            int idx = tid + i * THREADS;
            if constexpr (!TRANSB) {
                int k  = idx / (BN / 4);
                int nc = (idx % (BN / 4)) * 4;
                pb[i] = *reinterpret_cast<const float4*>(
                            &B[(size_t)(kt + k) * ldb + nBlock + nc]);
            } else {
                int n  = idx / KV;
                int kc = (idx % KV) * 4;
                pb[i] = *reinterpret_cast<const float4*>(
                            &B[(size_t)(nBlock + n) * ldb + kt + kc]);
            }
        }
    };

    auto storeTiles = [&]() {
#pragma unroll
        for (int i = 0; i < A_LOADS; i++) {
            int idx = tid + i * THREADS;
            int r   = idx / KV;
            int kc  = (idx % KV) * 4;
            As[kc + 0][r] = pa[i].x;
            As[kc + 1][r] = pa[i].y;
            As[kc + 2][r] = pa[i].z;
            As[kc + 3][r] = pa[i].w;
        }
#pragma unroll
        for (int i = 0; i < B_LOADS; i++) {
            int idx = tid + i * THREADS;
            if constexpr (!TRANSB) {
                int k  = idx / (BN / 4);
                int nc = (idx % (BN / 4)) * 4;
                *reinterpret_cast<float4*>(&Bs[k][nc]) = pb[i];
            } else {
                int n  = idx / KV;
                int kc = (idx % KV) * 4;
                Bs[kc + 0][n] = pb[i].x;
                Bs[kc + 1][n] = pb[i].y;
                Bs[kc + 2][n] = pb[i].z;
                Bs[kc + 3][n] = pb[i].w;
            }
        }
    };

    loadTiles(k0);
    const int kEnd = k0 + kChunk;
    for (int kt = k0; kt < kEnd; kt += BK) {
        storeTiles();
        __syncthreads();
        if (kt + BK < kEnd) loadTiles(kt + BK);

#pragma unroll
        for (int k = 0; k < BK; k++) {
            float a[TM], b[TN];
#pragma unroll
            for (int i = 0; i < TM; i++) a[i] = As[k][trow + i];
#pragma unroll
            for (int j = 0; j < TN; j++) b[j] = Bs[k][tcol + j];
#pragma unroll
            for (int i = 0; i < TM; i++)
#pragma unroll
                for (int j = 0; j < TN; j++)
                    acc[i][j] = fmaf(a[i], b[j], acc[i][j]);
        }
        __syncthreads();
    }

    // epilogue + vectorized store
#pragma unroll
    for (int i = 0; i < TM; i++) {
#pragma unroll
        for (int j = 0; j < TN; j += 4) {
            float4 v;
            v.x = acc[i][j + 0];
            v.y = acc[i][j + 1];
            v.z = acc[i][j + 2];
            v.w = acc[i][j + 3];
            if (epi == 1) {
                v.x = fmaxf(v.x, 0.f); v.y = fmaxf(v.y, 0.f);
                v.z = fmaxf(v.z, 0.f); v.w = fmaxf(v.w, 0.f);
            } else if (epi == 2) {
                v.x = expf(v.x); v.y = expf(v.y);
                v.z = expf(v.z); v.w = expf(v.w);
            }
            *reinterpret_cast<float4*>(
                &C[(size_t)(mBlock + trow + i) * ldc + nBlock + tcol + j]) = v;
        }
    }
}

// Split-K reduction: out[i] = epi(sum_z part[z*MN + i]); deterministic order.
__global__ void reduce_kernel(const float* __restrict__ part, float* __restrict__ out,
                              int MN, int splits, int epi)
{
    int i = (blockIdx.x * blockDim.x + threadIdx.x) * 4;
    if (i >= MN) return;
    float4 s = *reinterpret_cast<const float4*>(&part[i]);
    for (int z = 1; z < splits; z++) {
        float4 t = *reinterpret_cast<const float4*>(&part[(size_t)z * MN + i]);
        s.x += t.x; s.y += t.y; s.z += t.z; s.w += t.w;
    }
    if (epi == 1) {
        s.x = fmaxf(s.x, 0.f); s.y = fmaxf(s.y, 0.f);
        s.z = fmaxf(s.z, 0.f); s.w = fmaxf(s.w, 0.f);
    }
    *reinterpret_cast<float4*>(&out[i]) = s;
}

// ---------------------------------------------------------------------------
// Host-side launch helpers
// ---------------------------------------------------------------------------
static void gemm_big(const float* A, const float* B, float* C,
                     int M, int N, int K, int lda, int ldb, int ldc,
                     int splits, int epi)
{
    dim3 grid(N / 128, M / 128, splits);
    gemm_kernel<128, 128, 8, 8, 8, false><<<grid, 256>>>(
        A, B, C, M, N, K, lda, ldb, ldc, K / splits, epi);
}

static void gemm_big_nt(const float* A, const float* B, float* C,
                        int M, int N, int K, int lda, int ldb, int ldc, int epi)
{
    dim3 grid(N / 128, M / 128, 1);
    gemm_kernel<128, 128, 8, 8, 8, true><<<grid, 256>>>(
        A, B, C, M, N, K, lda, ldb, ldc, K, epi);
}

static void gemm_small(const float* A, const float* B, float* C,
                       int M, int N, int K, int lda, int ldb, int ldc, int epi)
{
    dim3 grid(N / 128, M / 64, 1);
    gemm_kernel<64, 128, 8, 8, 8, false><<<grid, 128>>>(
        A, B, C, M, N, K, lda, ldb, ldc, K, epi);
}

static void reduce_launch(const float* part, float* out, int MN, int splits, int epi)
{
    reduce_kernel<<<MN / (4 * 256), 256>>>(part, out, MN, splits, epi);
}

// One GCN branch: Xout = relu((A @ relu((A@X)@W1)) @ W2)
static void gcn_branch(const float* A, const float* X,
                       const float* W1, const float* W2,
                       float* Xout, float* split, float* bufAX, float* bufH)
{
    // 1. AX = A @ X   [4096,256], K=4096, split-K=4
    gemm_big(A, X, split, GN, DIN, GN, GN, DIN, DIN, 4, 0);
    reduce_launch(split, bufAX, GN * DIN, 4, 0);
    // 2. H = relu(AX @ W1)   [4096,128]
    gemm_small(bufAX, W1, bufH, GN, DH, DIN, DIN, DH, DH, 1);
    // 3. AH = A @ H   [4096,128], K=4096, split-K=8
    gemm_big(A, bufH, split, GN, DH, GN, GN, DH, DH, 8, 0);
    reduce_launch(split, bufAX, GN * DH, 8, 0);
    // 4. Xout = relu(AH @ W2)
    gemm_small(bufAX, W2, Xout, GN, DH, DH, DH, DH, DH, 1);
}

extern "C" void kernel_launch(void* const* d_in, const int* in_sizes, int n_in,
                              void* d_out, int out_size)
{
    const float* A_s = (const float*)d_in[0];
    const float* X_s = (const float*)d_in[1];
    const float* A_t = (const float*)d_in[2];
    const float* X_t = (const float*)d_in[3];
    const float* W1  = (const float*)d_in[4];
    const float* W2  = (const float*)d_in[5];
    const float* W3  = (const float*)d_in[6];
    const float* W4  = (const float*)d_in[7];

    float* out_s = (float*)d_out;                 // [4096, 128]
    float* out_t = out_s + (size_t)GN * DH;       // [4096, 128]
    float* S     = out_t + (size_t)GN * DH;       // [4096, 4096]

    float *split, *bufAX, *bufH, *bXs, *bXt, *bQ, *bPs, *bPt;
    cudaGetSymbolAddress((void**)&split, g_split);
    cudaGetSymbolAddress((void**)&bufAX, g_bufAX);
    cudaGetSymbolAddress((void**)&bufH,  g_bufH);
    cudaGetSymbolAddress((void**)&bXs,   g_Xs);
    cudaGetSymbolAddress((void**)&bXt,   g_Xt);
    cudaGetSymbolAddress((void**)&bQ,    g_Q);
    cudaGetSymbolAddress((void**)&bPs,   g_Ps);
    cudaGetSymbolAddress((void**)&bPt,   g_Pt);

    // GCN branches
    gcn_branch(A_s, X_s, W1, W2, bXs, split, bufAX, bufH);
    gcn_branch(A_t, X_t, W1, W2, bXt, split, bufAX, bufH);

    // Q = Xs @ W3   [4096,128]
    gemm_small(bXs, W3, bQ, GN, DH, DH, DH, DH, DH, 0);

    // S = exp(Q @ Xt^T)   [4096,4096]  (written straight into output)
    gemm_big_nt(bQ, bXt, S, GN, GN, DH, DH, DH, GN, 2);

    // Ps = S @ Xs, Pt = S @ Xt   [4096,128], K=4096, split-K=8
    gemm_big(S, bXs, split, GN, DH, GN, GN, DH, DH, 8, 0);
    reduce_launch(split, bPs, GN * DH, 8, 0);
    gemm_big(S, bXt, split, GN, DH, GN, GN, DH, DH, 8, 0);
    reduce_launch(split, bPt, GN * DH, 8, 0);

    // out_s = Ps @ W4, out_t = Pt @ W4
    gemm_small(bPs, W4, out_s, GN, DH, DH, DH, DH, DH, 0);
    gemm_small(bPt, W4, out_t, GN, DH, DH, DH, DH, DH, 0);
}

// round 3
// speedup vs baseline: 1.9818x; 1.9818x over previous
#include <cuda_runtime.h>
#include <math.h>
#include <stdint.h>

// ---------------------------------------------------------------------------
//   N = 4096, DIM_IN = 256, DIM_H = 128, DIM_OUT = 128
//   Xs = relu((A_s@X_s)@W1); Xs = relu((A_s@Xs)@W2)   (same for t)
//   S  = exp((Xs@W3)@Xt^T)
//   out_s = (S@Xs)@W4 ; out_t = (S@Xt)@W4
// Output: [out_s (4096*128) | out_t (4096*128) | S (4096*4096)]
// ---------------------------------------------------------------------------

#define GN    4096
#define DIN   256
#define DH    128

__device__ float g_split[4u * 4096u * 256u];   // split-K partials
__device__ float g_bufAX[4096 * 256];
__device__ float g_bufH [4096 * 128];
__device__ float g_Xs   [4096 * 128];
__device__ float g_Xt   [4096 * 128];
__device__ float g_Q    [4096 * 128];
__device__ float g_Ps   [4096 * 128];
__device__ float g_Pt   [4096 * 128];

// ---------------------------------------------------------------------------
// tf32 helpers
// ---------------------------------------------------------------------------
__device__ __forceinline__ uint32_t f2tf32(float x) {
    uint32_t r;
    asm("cvt.rna.tf32.f32 %0, %1;" : "=r"(r) : "f"(x));
    return r;
}

__device__ __forceinline__ void mma_tf32(float* c, const uint32_t* a, const uint32_t* b) {
    asm volatile(
        "mma.sync.aligned.m16n8k8.row.col.f32.tf32.tf32.f32 "
        "{%0,%1,%2,%3}, {%4,%5,%6,%7}, {%8,%9}, {%0,%1,%2,%3};\n"
        : "+f"(c[0]), "+f"(c[1]), "+f"(c[2]), "+f"(c[3])
        : "r"(a[0]), "r"(a[1]), "r"(a[2]), "r"(a[3]),
          "r"(b[0]), "r"(b[1]));
}

// ---------------------------------------------------------------------------
// tf32 tensor-core GEMM.
//   C[M,N] = A[M,K] @ B     (TRANSB=false: B is [K,N] row-major)
//                           (TRANSB=true : B is [N,K] row-major -> C = A @ B^T)
// CTA tile 128x128x32, 8 warps, warp tile 64x32 (m16n8k8).
// gridDim.z > 1 => split-K partials at C + z*M*N (epi must be 0).
// epi: 0 none, 1 relu, 2 exp
// ---------------------------------------------------------------------------
template <bool TRANSB>
__global__ void __launch_bounds__(256, 1)
mma_gemm(const float* __restrict__ A, const float* __restrict__ B,
         float* __restrict__ C,
         int M, int N, int K, int lda, int ldb, int ldc,
         int kChunk, int epi)
{
    constexpr int BM = 128, BN = 128, BK = 32;
    constexpr int THREADS = 256;
    constexpr int KV = BK / 4;                // 8
    constexpr int A_LOADS = (BM * KV) / THREADS;   // 4
    constexpr int B_LOADS = (BN * KV) / THREADS;   // 4
    constexpr int LDA_S = BM + 4;
    constexpr int LDB_S = BN + 4;

    __shared__ uint32_t As[BK * LDA_S];
    __shared__ uint32_t Bs[BK * LDB_S];

    const int tid  = threadIdx.x;
    const int lane = tid & 31;
    const int wid  = tid >> 5;
    const int wm   = wid & 1;                 // 2 warps along M
    const int wn   = wid >> 1;                // 4 warps along N
    const int g    = lane >> 2;               // group id 0..7
    const int t    = lane & 3;                // thread-in-group

    const int mBlock = blockIdx.y * BM;
    const int nBlock = blockIdx.x * BN;
    const int k0     = blockIdx.z * kChunk;

    if (gridDim.z > 1)
        C += (size_t)blockIdx.z * (size_t)M * (size_t)N;

    float4 pa[A_LOADS], pb[B_LOADS];

    float acc[4][4][4];
#pragma unroll
    for (int i = 0; i < 4; i++)
#pragma unroll
        for (int j = 0; j < 4; j++)
#pragma unroll
            for (int r = 0; r < 4; r++) acc[i][j][r] = 0.f;

    auto loadTiles = [&](int kt) {
#pragma unroll
        for (int i = 0; i < A_LOADS; i++) {
            int idx = tid + i * THREADS;
            int r   = idx / KV;
            int kc  = (idx % KV) * 4;
            pa[i] = *reinterpret_cast<const float4*>(
                        &A[(size_t)(mBlock + r) * lda + kt + kc]);
        }
#pragma unroll
        for (int i = 0; i < B_LOADS; i++) {
            int idx = tid + i * THREADS;
            if constexpr (!TRANSB) {
                int k  = idx / (BN / 4);
                int nc = (idx % (BN / 4)) * 4;
                pb[i] = *reinterpret_cast<const float4*>(
                            &B[(size_t)(kt + k) * ldb + nBlock + nc]);
            } else {
                int n  = idx / KV;
                int kc = (idx % KV) * 4;
                pb[i] = *reinterpret_cast<const float4*>(
                            &B[(size_t)(nBlock + n) * ldb + kt + kc]);
            }
        }
    };

    auto storeTiles = [&]() {
#pragma unroll
        for (int i = 0; i < A_LOADS; i++) {
            int idx = tid + i * THREADS;
            int r   = idx / KV;
            int kc  = (idx % KV) * 4;
            As[(kc + 0) * LDA_S + r] = f2tf32(pa[i].x);
            As[(kc + 1) * LDA_S + r] = f2tf32(pa[i].y);
            As[(kc + 2) * LDA_S + r] = f2tf32(pa[i].z);
            As[(kc + 3) * LDA_S + r] = f2tf32(pa[i].w);
        }
#pragma unroll
        for (int i = 0; i < B_LOADS; i++) {
            int idx = tid + i * THREADS;
            if constexpr (!TRANSB) {
                int k  = idx / (BN / 4);
                int nc = (idx % (BN / 4)) * 4;
                Bs[k * LDB_S + nc + 0] = f2tf32(pb[i].x);
                Bs[k * LDB_S + nc + 1] = f2tf32(pb[i].y);
                Bs[k * LDB_S + nc + 2] = f2tf32(pb[i].z);
                Bs[k * LDB_S + nc + 3] = f2tf32(pb[i].w);
            } else {
                int n  = idx / KV;
                int kc = (idx % KV) * 4;
                Bs[(kc + 0) * LDB_S + n] = f2tf32(pb[i].x);
                Bs[(kc + 1) * LDB_S + n] = f2tf32(pb[i].y);
                Bs[(kc + 2) * LDB_S + n] = f2tf32(pb[i].z);
                Bs[(kc + 3) * LDB_S + n] = f2tf32(pb[i].w);
            }
        }
    };

    loadTiles(k0);
    const int kEnd = k0 + kChunk;
    for (int kt = k0; kt < kEnd; kt += BK) {
        storeTiles();
        __syncthreads();
        if (kt + BK < kEnd) loadTiles(kt + BK);

#pragma unroll
        for (int ks = 0; ks < BK / 8; ks++) {
            const int kq = ks * 8 + t;
            uint32_t af[4][4], bf[4][2];
#pragma unroll
            for (int mt = 0; mt < 4; mt++) {
                int row = wm * 64 + mt * 16 + g;
                af[mt][0] = As[kq * LDA_S + row];
                af[mt][1] = As[kq * LDA_S + row + 8];
                af[mt][2] = As[(kq + 4) * LDA_S + row];
                af[mt][3] = As[(kq + 4) * LDA_S + row + 8];
            }
#pragma unroll
            for (int nt = 0; nt < 4; nt++) {
                int col = wn * 32 + nt * 8 + g;
                bf[nt][0] = Bs[kq * LDB_S + col];
                bf[nt][1] = Bs[(kq + 4) * LDB_S + col];
            }
#pragma unroll
            for (int mt = 0; mt < 4; mt++)
#pragma unroll
                for (int nt = 0; nt < 4; nt++)
                    mma_tf32(acc[mt][nt], af[mt], bf[nt]);
        }
        __syncthreads();
    }

    // epilogue
#pragma unroll
    for (int mt = 0; mt < 4; mt++) {
#pragma unroll
        for (int nt = 0; nt < 4; nt++) {
            int r0 = mBlock + wm * 64 + mt * 16 + g;
            int c0 = nBlock + wn * 32 + nt * 8 + 2 * t;
            float2 v0 = make_float2(acc[mt][nt][0], acc[mt][nt][1]);
            float2 v1 = make_float2(acc[mt][nt][2], acc[mt][nt][3]);
            if (epi == 1) {
                v0.x = fmaxf(v0.x, 0.f); v0.y = fmaxf(v0.y, 0.f);
                v1.x = fmaxf(v1.x, 0.f); v1.y = fmaxf(v1.y, 0.f);
            } else if (epi == 2) {
                v0.x = expf(v0.x); v0.y = expf(v0.y);
                v1.x = expf(v1.x); v1.y = expf(v1.y);
            }
            *reinterpret_cast<float2*>(&C[(size_t)r0 * ldc + c0]) = v0;
            *reinterpret_cast<float2*>(&C[(size_t)(r0 + 8) * ldc + c0]) = v1;
        }
    }
}

// Split-K reduction (deterministic order).
__global__ void reduce_kernel(const float* __restrict__ part, float* __restrict__ out,
                              int MN, int splits, int epi)
{
    int i = (blockIdx.x * blockDim.x + threadIdx.x) * 4;
    if (i >= MN) return;
    float4 s = *reinterpret_cast<const float4*>(&part[i]);
    for (int z = 1; z < splits; z++) {
        float4 tt = *reinterpret_cast<const float4*>(&part[(size_t)z * MN + i]);
        s.x += tt.x; s.y += tt.y; s.z += tt.z; s.w += tt.w;
    }
    if (epi == 1) {
        s.x = fmaxf(s.x, 0.f); s.y = fmaxf(s.y, 0.f);
        s.z = fmaxf(s.z, 0.f); s.w = fmaxf(s.w, 0.f);
    }
    *reinterpret_cast<float4*>(&out[i]) = s;
}

// ---------------------------------------------------------------------------
// Launch helpers
// ---------------------------------------------------------------------------
template <bool TB>
static void mma_launch(const float* A, const float* B, float* C,
                       int M, int N, int K, int lda, int ldb, int ldc,
                       int splits, int epi)
{
    dim3 grid(N / 128, M / 128, splits);
    mma_gemm<TB><<<grid, 256>>>(A, B, C, M, N, K, lda, ldb, ldc, K / splits, epi);
}

static void reduce_launch(const float* part, float* out, int MN, int splits, int epi)
{
    reduce_kernel<<<MN / (4 * 256), 256>>>(part, out, MN, splits, epi);
}

// One GCN branch: Xout = relu((A @ relu((A@X)@W1)) @ W2)
static void gcn_branch(const float* A, const float* X,
                       const float* W1, const float* W2,
                       float* Xout, float* split, float* bufAX, float* bufH)
{
    // AX = A @ X  [4096,256] K=4096, split-K=2 -> 128 CTAs (1 wave)
    mma_launch<false>(A, X, split, GN, DIN, GN, GN, DIN, DIN, 2, 0);
    reduce_launch(split, bufAX, GN * DIN, 2, 0);
    // H = relu(AX @ W1)  [4096,128] K=256
    mma_launch<false>(bufAX, W1, bufH, GN, DH, DIN, DIN, DH, DH, 1, 1);
    // AH = A @ H  [4096,128] K=4096, split-K=4 -> 128 CTAs
    mma_launch<false>(A, bufH, split, GN, DH, GN, GN, DH, DH, 4, 0);
    reduce_launch(split, bufAX, GN * DH, 4, 0);
    // Xout = relu(AH @ W2)  K=128
    mma_launch<false>(bufAX, W2, Xout, GN, DH, DH, DH, DH, DH, 1, 1);
}

extern "C" void kernel_launch(void* const* d_in, const int* in_sizes, int n_in,
                              void* d_out, int out_size)
{
    const float* A_s = (const float*)d_in[0];
    const float* X_s = (const float*)d_in[1];
    const float* A_t = (const float*)d_in[2];
    const float* X_t = (const float*)d_in[3];
    const float* W1  = (const float*)d_in[4];
    const float* W2  = (const float*)d_in[5];
    const float* W3  = (const float*)d_in[6];
    const float* W4  = (const float*)d_in[7];

    float* out_s = (float*)d_out;
    float* out_t = out_s + (size_t)GN * DH;
    float* S     = out_t + (size_t)GN * DH;

    float *split, *bufAX, *bufH, *bXs, *bXt, *bQ, *bPs, *bPt;
    cudaGetSymbolAddress((void**)&split, g_split);
    cudaGetSymbolAddress((void**)&bufAX, g_bufAX);
    cudaGetSymbolAddress((void**)&bufH,  g_bufH);
    cudaGetSymbolAddress((void**)&bXs,   g_Xs);
    cudaGetSymbolAddress((void**)&bXt,   g_Xt);
    cudaGetSymbolAddress((void**)&bQ,    g_Q);
    cudaGetSymbolAddress((void**)&bPs,   g_Ps);
    cudaGetSymbolAddress((void**)&bPt,   g_Pt);

    // GCN branches
    gcn_branch(A_s, X_s, W1, W2, bXs, split, bufAX, bufH);
    gcn_branch(A_t, X_t, W1, W2, bXt, split, bufAX, bufH);

    // Q = Xs @ W3  [4096,128] K=128
    mma_launch<false>(bXs, W3, bQ, GN, DH, DH, DH, DH, DH, 1, 0);

    // S = exp(Q @ Xt^T)  [4096,4096] K=128
    mma_launch<true>(bQ, bXt, S, GN, GN, DH, DH, DH, GN, 1, 2);

    // Ps = S @ Xs, Pt = S @ Xt  [4096,128] K=4096, split-K=4
    mma_launch<false>(S, bXs, split, GN, DH, GN, GN, DH, DH, 4, 0);
    reduce_launch(split, bPs, GN * DH, 4, 0);
    mma_launch<false>(S, bXt, split, GN, DH, GN, GN, DH, DH, 4, 0);
    reduce_launch(split, bPt, GN * DH, 4, 0);

    // out_s = Ps @ W4, out_t = Pt @ W4  K=128
    mma_launch<false>(bPs, W4, out_s, GN, DH, DH, DH, DH, DH, 1, 0);
    mma_launch<false>(bPt, W4, out_t, GN, DH, DH, DH, DH, DH, 1, 0);
}

// round 4
// speedup vs baseline: 2.4748x; 1.2487x over previous
#include <cuda_runtime.h>
#include <math.h>
#include <stdint.h>

// ---------------------------------------------------------------------------
//   N = 4096, DIM_IN = 256, DIM_H = 128, DIM_OUT = 128
//   Xs = relu((A_s@X_s)@W1); Xs = relu((A_s@Xs)@W2)   (same for t)
//   S  = exp((Xs@W3)@Xt^T)
//   out_s = (S@Xs)@W4 ; out_t = (S@Xt)@W4
// Output: [out_s | out_t | S]
// ---------------------------------------------------------------------------

#define GN    4096
#define DIN   256
#define DH    128

__device__ float g_split[4u * 4096u * 256u];   // split-K partials
__device__ float g_bufAX[4096 * 256];          // A@X intermediate / XsXt pack
__device__ float g_bufH [4096 * 128];
__device__ float g_Xs   [4096 * 128];
__device__ float g_Xt   [4096 * 128];
__device__ float g_Q    [4096 * 128];
__device__ float g_P    [8192 * 128];          // [Ps; Pt] stacked

// ---------------------------------------------------------------------------
// tf32 helpers
// ---------------------------------------------------------------------------
__device__ __forceinline__ uint32_t f2tf32(float x) {
    uint32_t r;
    asm("cvt.rna.tf32.f32 %0, %1;" : "=r"(r) : "f"(x));
    return r;
}

__device__ __forceinline__ void mma_tf32(float* c, const uint32_t* a, const uint32_t* b) {
    asm volatile(
        "mma.sync.aligned.m16n8k8.row.col.f32.tf32.tf32.f32 "
        "{%0,%1,%2,%3}, {%4,%5,%6,%7}, {%8,%9}, {%0,%1,%2,%3};\n"
        : "+f"(c[0]), "+f"(c[1]), "+f"(c[2]), "+f"(c[3])
        : "r"(a[0]), "r"(a[1]), "r"(a[2]), "r"(a[3]),
          "r"(b[0]), "r"(b[1]));
}

// ---------------------------------------------------------------------------
// tf32 tensor-core GEMM, fragment-packed smem, double buffered.
//   C[M,N] = A[M,K] @ B   (TRANSB=false: B [K,N] row-major; true: B [N,K] -> A@B^T)
// CTA tile 128x128x32, 8 warps (2M x 4N), warp tile 64x32 (m16n8k8).
// Packed A smem: [ks(4)][rb(8)][lane(32)][slot(4)] words, +4 pad per ks plane.
//   slot = (k_hi?2:0) + (row_hi8?1:0)  -> LDS.128 per fragment, conflict-free.
// Packed B smem: [ks(4)][nb(16)][lane(32)*2+slot(2)] with nb stride 66 words.
// gridDim.z > 1 => split-K partials at C + z*M*N (epi must be 0).
// epi: 0 none, 1 relu, 2 exp
// ---------------------------------------------------------------------------
constexpr int A_WORDS = 4 * (8 * 32 * 4 + 4);   // 4*1028 = 4112
constexpr int B_WORDS = 4 * (16 * 66);          // 4*1056 = 4224
constexpr int SMEM_BYTES = (2 * A_WORDS + 2 * B_WORDS) * 4;  // 66,688 B

template <bool TRANSB>
__global__ void __launch_bounds__(256, 1)
mma_gemm(const float* __restrict__ A, const float* __restrict__ B,
         float* __restrict__ C,
         int M, int N, int K, int lda, int ldb, int ldc,
         int kChunk, int epi)
{
    constexpr int BM = 128, BN = 128, BK = 32;
    constexpr int THREADS = 256;
    constexpr int KV = BK / 4;                      // 8
    constexpr int A_LOADS = (BM * KV) / THREADS;    // 4
    constexpr int B_LOADS = (BN * KV) / THREADS;    // 4

    extern __shared__ uint32_t sm[];
    uint32_t* AsBase = sm;                  // [2][A_WORDS]
    uint32_t* BsBase = sm + 2 * A_WORDS;    // [2][B_WORDS]

    const int tid  = threadIdx.x;
    const int lane = tid & 31;
    const int wid  = tid >> 5;
    const int wm   = wid & 1;
    const int wn   = wid >> 1;

    const int mBlock = blockIdx.y * BM;
    const int nBlock = blockIdx.x * BN;
    const int k0     = blockIdx.z * kChunk;

    if (gridDim.z > 1)
        C += (size_t)blockIdx.z * (size_t)M * (size_t)N;

    float4 pa[A_LOADS], pb[B_LOADS];

    float acc[4][4][4];
#pragma unroll
    for (int i = 0; i < 4; i++)
#pragma unroll
        for (int j = 0; j < 4; j++)
#pragma unroll
            for (int r = 0; r < 4; r++) acc[i][j][r] = 0.f;

    auto loadTiles = [&](int kt) {
#pragma unroll
        for (int i = 0; i < A_LOADS; i++) {
            int idx = tid + i * THREADS;
            int r   = idx >> 3;
            int kc  = (idx & 7) * 4;
            pa[i] = *reinterpret_cast<const float4*>(
                        &A[(size_t)(mBlock + r) * lda + kt + kc]);
        }
#pragma unroll
        for (int i = 0; i < B_LOADS; i++) {
            int idx = tid + i * THREADS;
            if constexpr (!TRANSB) {
                int k  = idx >> 5;
                int nc = (idx & 31) * 4;
                pb[i] = *reinterpret_cast<const float4*>(
                            &B[(size_t)(kt + k) * ldb + nBlock + nc]);
            } else {
                int n  = idx >> 3;
                int kc = (idx & 7) * 4;
                pb[i] = *reinterpret_cast<const float4*>(
                            &B[(size_t)(nBlock + n) * ldb + kt + kc]);
            }
        }
    };

    auto storeTiles = [&](int buf) {
        uint32_t* As = AsBase + buf * A_WORDS;
        uint32_t* Bs = BsBase + buf * B_WORDS;
#pragma unroll
        for (int i = 0; i < A_LOADS; i++) {
            int idx = tid + i * THREADS;
            int R   = idx >> 3;
            int kc  = (idx & 7) * 4;
            int ks   = kc >> 3;
            int shi  = (kc >> 2) & 1;
            int rb   = R >> 4;
            int slot = shi * 2 + ((R >> 3) & 1);
            int lb   = (R & 7) * 4;
            uint32_t* p = As + ks * 1028 + rb * 128 + slot;
            p[(lb + 0) * 4] = f2tf32(pa[i].x);
            p[(lb + 1) * 4] = f2tf32(pa[i].y);
            p[(lb + 2) * 4] = f2tf32(pa[i].z);
            p[(lb + 3) * 4] = f2tf32(pa[i].w);
        }
#pragma unroll
        for (int i = 0; i < B_LOADS; i++) {
            int idx = tid + i * THREADS;
            if constexpr (!TRANSB) {
                int k  = idx >> 5;
                int nc = (idx & 31) * 4;
                int ks   = k >> 3;
                int tt   = k & 7;
                int slot = tt >> 2;
                int t    = tt & 3;
                int nb   = nc >> 3;
                int g0   = nc & 7;              // 0 or 4
                uint32_t* p = Bs + ks * 1056 + nb * 66 + slot;
                p[((g0 + 0) * 4 + t) * 2] = f2tf32(pb[i].x);
                p[((g0 + 1) * 4 + t) * 2] = f2tf32(pb[i].y);
                p[((g0 + 2) * 4 + t) * 2] = f2tf32(pb[i].z);
                p[((g0 + 3) * 4 + t) * 2] = f2tf32(pb[i].w);
            } else {
                int n  = idx >> 3;
                int kc = (idx & 7) * 4;
                int ks   = kc >> 3;
                int slot = (kc >> 2) & 1;
                int nb   = n >> 3;
                int g    = n & 7;
                uint32_t* p = Bs + ks * 1056 + nb * 66 + slot;
                p[(g * 4 + 0) * 2] = f2tf32(pb[i].x);
                p[(g * 4 + 1) * 2] = f2tf32(pb[i].y);
                p[(g * 4 + 2) * 2] = f2tf32(pb[i].z);
                p[(g * 4 + 3) * 2] = f2tf32(pb[i].w);
            }
        }
    };

    auto computeTile = [&](int buf) {
        const uint32_t* As = AsBase + buf * A_WORDS;
        const uint32_t* Bs = BsBase + buf * B_WORDS;
#pragma unroll
        for (int ks = 0; ks < 4; ks++) {
            uint32_t af[4][4], bf[4][2];
#pragma unroll
            for (int mt = 0; mt < 4; mt++) {
                uint4 v = *reinterpret_cast<const uint4*>(
                    As + ks * 1028 + (wm * 4 + mt) * 128 + lane * 4);
                af[mt][0] = v.x; af[mt][1] = v.y; af[mt][2] = v.z; af[mt][3] = v.w;
            }
#pragma unroll
            for (int nt = 0; nt < 4; nt++) {
                uint2 v = *reinterpret_cast<const uint2*>(
                    Bs + ks * 1056 + (wn * 4 + nt) * 66 + lane * 2);
                bf[nt][0] = v.x; bf[nt][1] = v.y;
            }
#pragma unroll
            for (int mt = 0; mt < 4; mt++)
#pragma unroll
                for (int nt = 0; nt < 4; nt++)
                    mma_tf32(acc[mt][nt], af[mt], bf[nt]);
        }
    };

    const int kEnd = k0 + kChunk;
    loadTiles(k0);
    storeTiles(0);
    __syncthreads();
    int buf = 0;
    for (int kt = k0; kt < kEnd; kt += BK) {
        bool last = (kt + BK >= kEnd);
        if (!last) loadTiles(kt + BK);
        computeTile(buf);
        if (!last) {
            storeTiles(buf ^ 1);
            __syncthreads();
            buf ^= 1;
        }
    }

    const int g = lane >> 2;
    const int t = lane & 3;
#pragma unroll
    for (int mt = 0; mt < 4; mt++) {
#pragma unroll
        for (int nt = 0; nt < 4; nt++) {
            int r0 = mBlock + wm * 64 + mt * 16 + g;
            int c0 = nBlock + wn * 32 + nt * 8 + 2 * t;
            float2 v0 = make_float2(acc[mt][nt][0], acc[mt][nt][1]);
            float2 v1 = make_float2(acc[mt][nt][2], acc[mt][nt][3]);
            if (epi == 1) {
                v0.x = fmaxf(v0.x, 0.f); v0.y = fmaxf(v0.y, 0.f);
                v1.x = fmaxf(v1.x, 0.f); v1.y = fmaxf(v1.y, 0.f);
            } else if (epi == 2) {
                v0.x = expf(v0.x); v0.y = expf(v0.y);
                v1.x = expf(v1.x); v1.y = expf(v1.y);
            }
            *reinterpret_cast<float2*>(&C[(size_t)r0 * ldc + c0]) = v0;
            *reinterpret_cast<float2*>(&C[(size_t)(r0 + 8) * ldc + c0]) = v1;
        }
    }
}

// Split-K reduction (deterministic order).
__global__ void reduce_kernel(const float* __restrict__ part, float* __restrict__ out,
                              int MN, int splits)
{
    int i = (blockIdx.x * blockDim.x + threadIdx.x) * 4;
    if (i >= MN) return;
    float4 s = *reinterpret_cast<const float4*>(&part[i]);
    for (int z = 1; z < splits; z++) {
        float4 t = *reinterpret_cast<const float4*>(&part[(size_t)z * MN + i]);
        s.x += t.x; s.y += t.y; s.z += t.z; s.w += t.w;
    }
    *reinterpret_cast<float4*>(&out[i]) = s;
}

// Split-K reduce + de-interleave: part [z][4096][256] -> out [8192][128]
// (cols 0..127 -> rows 0..4095, cols 128..255 -> rows 4096..8191)
__global__ void reduce_deint_kernel(const float* __restrict__ part, float* __restrict__ out,
                                    int splits)
{
    int o = (blockIdx.x * blockDim.x + threadIdx.x) * 4;   // over 8192*128
    int r = o >> 7;
    int c = o & 127;
    size_t src = (size_t)(r & 4095) * 256 + ((r >> 12) << 7) + c;
    const int MN = 4096 * 256;
    float4 s = *reinterpret_cast<const float4*>(&part[src]);
    for (int z = 1; z < splits; z++) {
        float4 t = *reinterpret_cast<const float4*>(&part[(size_t)z * MN + src]);
        s.x += t.x; s.y += t.y; s.z += t.z; s.w += t.w;
    }
    *reinterpret_cast<float4*>(&out[o]) = s;
}

// Pack [Xs | Xt] -> out [4096][256]
__global__ void pack_kernel(const float* __restrict__ Xs, const float* __restrict__ Xt,
                            float* __restrict__ out)
{
    int o = (blockIdx.x * blockDim.x + threadIdx.x) * 4;   // over 4096*256
    int r = o >> 8;
    int c = o & 255;
    float4 v = (c < 128)
        ? *reinterpret_cast<const float4*>(&Xs[(size_t)r * 128 + c])
        : *reinterpret_cast<const float4*>(&Xt[(size_t)r * 128 + (c - 128)]);
    *reinterpret_cast<float4*>(&out[o]) = v;
}

// ---------------------------------------------------------------------------
// Launch helpers
// ---------------------------------------------------------------------------
template <bool TB>
static void mma_launch(const float* A, const float* B, float* C,
                       int M, int N, int K, int lda, int ldb, int ldc,
                       int splits, int epi)
{
    cudaFuncSetAttribute(mma_gemm<TB>, cudaFuncAttributeMaxDynamicSharedMemorySize,
                         SMEM_BYTES);
    dim3 grid(N / 128, M / 128, splits);
    mma_gemm<TB><<<grid, 256, SMEM_BYTES>>>(A, B, C, M, N, K, lda, ldb, ldc,
                                            K / splits, epi);
}

static void reduce_launch(const float* part, float* out, int MN, int splits)
{
    reduce_kernel<<<MN / (4 * 256), 256>>>(part, out, MN, splits);
}

// One GCN branch: Xout = relu((A @ relu((A@X)@W1)) @ W2)
static void gcn_branch(const float* A, const float* X,
                       const float* W1, const float* W2,
                       float* Xout, float* split, float* bufAX, float* bufH)
{
    mma_launch<false>(A, X, split, GN, DIN, GN, GN, DIN, DIN, 2, 0);
    reduce_launch(split, bufAX, GN * DIN, 2);
    mma_launch<false>(bufAX, W1, bufH, GN, DH, DIN, DIN, DH, DH, 1, 1);
    mma_launch<false>(A, bufH, split, GN, DH, GN, GN, DH, DH, 4, 0);
    reduce_launch(split, bufAX, GN * DH, 4);
    mma_launch<false>(bufAX, W2, Xout, GN, DH, DH, DH, DH, DH, 1, 1);
}

extern "C" void kernel_launch(void* const* d_in, const int* in_sizes, int n_in,
                              void* d_out, int out_size)
{
    const float* A_s = (const float*)d_in[0];
    const float* X_s = (const float*)d_in[1];
    const float* A_t = (const float*)d_in[2];
    const float* X_t = (const float*)d_in[3];
    const float* W1  = (const float*)d_in[4];
    const float* W2  = (const float*)d_in[5];
    const float* W3  = (const float*)d_in[6];
    const float* W4  = (const float*)d_in[7];

    float* out_st = (float*)d_out;                       // [8192, 128] = out_s|out_t
    float* S      = out_st + (size_t)2 * GN * DH;        // [4096, 4096]

    float *split, *bufAX, *bufH, *bXs, *bXt, *bQ, *bP;
    cudaGetSymbolAddress((void**)&split, g_split);
    cudaGetSymbolAddress((void**)&bufAX, g_bufAX);
    cudaGetSymbolAddress((void**)&bufH,  g_bufH);
    cudaGetSymbolAddress((void**)&bXs,   g_Xs);
    cudaGetSymbolAddress((void**)&bXt,   g_Xt);
    cudaGetSymbolAddress((void**)&bQ,    g_Q);
    cudaGetSymbolAddress((void**)&bP,    g_P);

    // GCN branches
    gcn_branch(A_s, X_s, W1, W2, bXs, split, bufAX, bufH);
    gcn_branch(A_t, X_t, W1, W2, bXt, split, bufAX, bufH);

    // Q = Xs @ W3
    mma_launch<false>(bXs, W3, bQ, GN, DH, DH, DH, DH, DH, 1, 0);

    // S = exp(Q @ Xt^T)  (written straight into output)
    mma_launch<true>(bQ, bXt, S, GN, GN, DH, DH, DH, GN, 1, 2);

    // XsXt = [Xs | Xt]  [4096, 256]  (reuse bufAX)
    pack_kernel<<<GN * 256 / (4 * 256), 256>>>(bXs, bXt, bufAX);

    // P_pair = S @ [Xs|Xt]  [4096,256], K=4096, split-K=4 (one pass over S)
    mma_launch<false>(S, bufAX, split, GN, 2 * DH, GN, GN, 2 * DH, 2 * DH, 4, 0);
    reduce_deint_kernel<<<8192 * 128 / (4 * 256), 256>>>(split, bP, 4);

    // [out_s; out_t] = [Ps; Pt] @ W4   (M = 8192, writes d_out directly)
    mma_launch<false>(bP, W4, out_st, 2 * GN, DH, DH, DH, DH, DH, 1, 0);
}

// round 7
// speedup vs baseline: 2.6715x; 1.0795x over previous
#include <cuda_runtime.h>
#include <math.h>
#include <stdint.h>

// ---------------------------------------------------------------------------
//   N = 4096, DIM_IN = 256, DIM_H = 128, DIM_OUT = 128
//   Xs = relu((A_s@X_s)@W1); Xs = relu((A_s@Xs)@W2)   (same for t)
//   S  = exp((Xs@W3)@Xt^T)
//   out_s = (S@Xs)@W4 ; out_t = (S@Xt)@W4
// Output: [out_s | out_t | S]
// NOTE: tcgen05 is NOT available — harness compiles PTX to .target sm_103
// (no 'a' suffix); arch-specific instructions fail ptxas. HMMA mma.sync only.
// ---------------------------------------------------------------------------

#define GN    4096
#define DIN   256
#define DH    128

__device__ float g_split[4u * 4096u * 256u];   // split-K partials
__device__ float g_bufAX[4096 * 256];          // A@X intermediate / XsXt pack
__device__ float g_bufH [4096 * 128];
__device__ float g_Xs   [4096 * 128];
__device__ float g_Xt   [4096 * 128];
__device__ float g_Q    [4096 * 128];
__device__ float g_P    [8192 * 128];          // [Ps; Pt] stacked

// ---------------------------------------------------------------------------
// helpers
// ---------------------------------------------------------------------------
__device__ __forceinline__ uint32_t f2tf32(float x) {
    uint32_t r;
    asm("cvt.rna.tf32.f32 %0, %1;" : "=r"(r) : "f"(x));
    return r;
}

__device__ __forceinline__ void mma_tf32(float* c, const uint32_t* a, const uint32_t* b) {
    asm volatile(
        "mma.sync.aligned.m16n8k8.row.col.f32.tf32.tf32.f32 "
        "{%0,%1,%2,%3}, {%4,%5,%6,%7}, {%8,%9}, {%0,%1,%2,%3};\n"
        : "+f"(c[0]), "+f"(c[1]), "+f"(c[2]), "+f"(c[3])
        : "r"(a[0]), "r"(a[1]), "r"(a[2]), "r"(a[3]),
          "r"(b[0]), "r"(b[1]));
}

// FFMA-only exp: avoids the MUFU pipe entirely (16.7M exps would otherwise be
// MUFU-throughput-bound at ~125us chip-wide). Inputs are bounded by problem
// construction (no overflow per reference), |t| << 2^22 so the magic-round is
// exact; poly trunc error ~1e-7 over r in [-0.5,0.5].
__device__ __forceinline__ float fast_exp(float x) {
    const float LOG2E = 1.4426950408889634f;
    float t  = x * LOG2E;
    float kf = t + 12582912.0f;                 // 2^23 + 2^22: round-to-nearest-int
    int   k  = __float_as_int(kf) - 0x4B400000; // integer part
    float r  = t - (kf - 12582912.0f);          // r in [-0.5, 0.5]
    // 2^r Taylor, degree 6
    float p = 1.5403530e-4f;
    p = fmaf(p, r, 1.3333558e-3f);
    p = fmaf(p, r, 9.6181291e-3f);
    p = fmaf(p, r, 5.5504109e-2f);
    p = fmaf(p, r, 2.4022651e-1f);
    p = fmaf(p, r, 6.9314718e-1f);
    p = fmaf(p, r, 1.0f);
    return __int_as_float(__float_as_int(p) + (k << 23));
}

// ---------------------------------------------------------------------------
// tf32 tensor-core GEMM, fragment-packed smem, double buffered.
//   C[M,N] = A[M,K] @ B   (TRANSB=false: B [K,N] row-major; true: B [N,K] -> A@B^T)
// CTA tile 128x128x32, 512 threads = 16 warps (4M x 4N), warp tile 32x32.
// Packed A smem: [ks(4)][rb(8)][lane(32)][slot(4)] words, +4 pad per ks plane.
// Packed B smem: [ks(4)][nb(16)][lane(32)*2+slot(2)] with nb stride 66 words.
// gridDim.z > 1 => split-K partials at C + z*M*N (epi must be 0).
// epi: 0 none, 1 relu, 2 exp
// ---------------------------------------------------------------------------
constexpr int A_WORDS = 4 * (8 * 32 * 4 + 4);   // 4*1028 = 4112
constexpr int B_WORDS = 4 * (16 * 66);          // 4*1056 = 4224
constexpr int SMEM_BYTES = (2 * A_WORDS + 2 * B_WORDS) * 4;  // 66,688 B

template <bool TRANSB>
__global__ void __launch_bounds__(512, 1)
mma_gemm(const float* __restrict__ A, const float* __restrict__ B,
         float* __restrict__ C,
         int M, int N, int K, int lda, int ldb, int ldc,
         int kChunk, int epi)
{
    constexpr int BM = 128, BN = 128, BK = 32;
    constexpr int THREADS = 512;
    constexpr int KV = BK / 4;                      // 8
    constexpr int A_LOADS = (BM * KV) / THREADS;    // 2
    constexpr int B_LOADS = (BN * KV) / THREADS;    // 2

    extern __shared__ uint32_t sm[];
    uint32_t* AsBase = sm;                  // [2][A_WORDS]
    uint32_t* BsBase = sm + 2 * A_WORDS;    // [2][B_WORDS]

    const int tid  = threadIdx.x;
    const int lane = tid & 31;
    const int wid  = tid >> 5;
    const int wm   = wid & 3;               // 4 warps along M
    const int wn   = wid >> 2;              // 4 warps along N

    const int mBlock = blockIdx.y * BM;
    const int nBlock = blockIdx.x * BN;
    const int k0     = blockIdx.z * kChunk;

    if (gridDim.z > 1)
        C += (size_t)blockIdx.z * (size_t)M * (size_t)N;

    float4 pa[A_LOADS], pb[B_LOADS];

    float acc[2][4][4];
#pragma unroll
    for (int i = 0; i < 2; i++)
#pragma unroll
        for (int j = 0; j < 4; j++)
#pragma unroll
            for (int r = 0; r < 4; r++) acc[i][j][r] = 0.f;

    auto loadTiles = [&](int kt) {
#pragma unroll
        for (int i = 0; i < A_LOADS; i++) {
            int idx = tid + i * THREADS;
            int r   = idx >> 3;
            int kc  = (idx & 7) * 4;
            pa[i] = *reinterpret_cast<const float4*>(
                        &A[(size_t)(mBlock + r) * lda + kt + kc]);
        }
#pragma unroll
        for (int i = 0; i < B_LOADS; i++) {
            int idx = tid + i * THREADS;
            if constexpr (!TRANSB) {
                int k  = idx >> 5;
                int nc = (idx & 31) * 4;
                pb[i] = *reinterpret_cast<const float4*>(
                            &B[(size_t)(kt + k) * ldb + nBlock + nc]);
            } else {
                int n  = idx >> 3;
                int kc = (idx & 7) * 4;
                pb[i] = *reinterpret_cast<const float4*>(
                            &B[(size_t)(nBlock + n) * ldb + kt + kc]);
            }
        }
    };

    auto storeTiles = [&](int buf) {
        uint32_t* As = AsBase + buf * A_WORDS;
        uint32_t* Bs = BsBase + buf * B_WORDS;
#pragma unroll
        for (int i = 0; i < A_LOADS; i++) {
            int idx = tid + i * THREADS;
            int R   = idx >> 3;
            int kc  = (idx & 7) * 4;
            int ks   = kc >> 3;
            int shi  = (kc >> 2) & 1;
            int rb   = R >> 4;
            int slot = shi * 2 + ((R >> 3) & 1);
            int lb   = (R & 7) * 4;
            uint32_t* p = As + ks * 1028 + rb * 128 + slot;
            p[(lb + 0) * 4] = f2tf32(pa[i].x);
            p[(lb + 1) * 4] = f2tf32(pa[i].y);
            p[(lb + 2) * 4] = f2tf32(pa[i].z);
            p[(lb + 3) * 4] = f2tf32(pa[i].w);
        }
#pragma unroll
        for (int i = 0; i < B_LOADS; i++) {
            int idx = tid + i * THREADS;
            if constexpr (!TRANSB) {
                int k  = idx >> 5;
                int nc = (idx & 31) * 4;
                int ks   = k >> 3;
                int tt   = k & 7;
                int slot = tt >> 2;
                int t    = tt & 3;
                int nb   = nc >> 3;
                int g0   = nc & 7;              // 0 or 4
                uint32_t* p = Bs + ks * 1056 + nb * 66 + slot;
                p[((g0 + 0) * 4 + t) * 2] = f2tf32(pb[i].x);
                p[((g0 + 1) * 4 + t) * 2] = f2tf32(pb[i].y);
                p[((g0 + 2) * 4 + t) * 2] = f2tf32(pb[i].z);
                p[((g0 + 3) * 4 + t) * 2] = f2tf32(pb[i].w);
            } else {
                int n  = idx >> 3;
                int kc = (idx & 7) * 4;
                int ks   = kc >> 3;
                int slot = (kc >> 2) & 1;
                int nb   = n >> 3;
                int g    = n & 7;
                uint32_t* p = Bs + ks * 1056 + nb * 66 + slot;
                p[(g * 4 + 0) * 2] = f2tf32(pb[i].x);
                p[(g * 4 + 1) * 2] = f2tf32(pb[i].y);
                p[(g * 4 + 2) * 2] = f2tf32(pb[i].z);
                p[(g * 4 + 3) * 2] = f2tf32(pb[i].w);
            }
        }
    };

    auto computeTile = [&](int buf) {
        const uint32_t* As = AsBase + buf * A_WORDS;
        const uint32_t* Bs = BsBase + buf * B_WORDS;
#pragma unroll
        for (int ks = 0; ks < 4; ks++) {
            uint32_t af[2][4], bf[4][2];
#pragma unroll
            for (int mt = 0; mt < 2; mt++) {
                uint4 v = *reinterpret_cast<const uint4*>(
                    As + ks * 1028 + (wm * 2 + mt) * 128 + lane * 4);
                af[mt][0] = v.x; af[mt][1] = v.y; af[mt][2] = v.z; af[mt][3] = v.w;
            }
#pragma unroll
            for (int nt = 0; nt < 4; nt++) {
                uint2 v = *reinterpret_cast<const uint2*>(
                    Bs + ks * 1056 + (wn * 4 + nt) * 66 + lane * 2);
                bf[nt][0] = v.x; bf[nt][1] = v.y;
            }
#pragma unroll
            for (int mt = 0; mt < 2; mt++)
#pragma unroll
                for (int nt = 0; nt < 4; nt++)
                    mma_tf32(acc[mt][nt], af[mt], bf[nt]);
        }
    };

    const int kEnd = k0 + kChunk;
    loadTiles(k0);
    storeTiles(0);
    __syncthreads();
    int buf = 0;
    for (int kt = k0; kt < kEnd; kt += BK) {
        bool last = (kt + BK >= kEnd);
        if (!last) loadTiles(kt + BK);
        computeTile(buf);
        if (!last) {
            storeTiles(buf ^ 1);
            __syncthreads();
            buf ^= 1;
        }
    }

    const int g = lane >> 2;
    const int t = lane & 3;
#pragma unroll
    for (int mt = 0; mt < 2; mt++) {
#pragma unroll
        for (int nt = 0; nt < 4; nt++) {
            int r0 = mBlock + wm * 32 + mt * 16 + g;
            int c0 = nBlock + wn * 32 + nt * 8 + 2 * t;
            float2 v0 = make_float2(acc[mt][nt][0], acc[mt][nt][1]);
            float2 v1 = make_float2(acc[mt][nt][2], acc[mt][nt][3]);
            if (epi == 1) {
                v0.x = fmaxf(v0.x, 0.f); v0.y = fmaxf(v0.y, 0.f);
                v1.x = fmaxf(v1.x, 0.f); v1.y = fmaxf(v1.y, 0.f);
            } else if (epi == 2) {
                v0.x = fast_exp(v0.x); v0.y = fast_exp(v0.y);
                v1.x = fast_exp(v1.x); v1.y = fast_exp(v1.y);
            }
            *reinterpret_cast<float2*>(&C[(size_t)r0 * ldc + c0]) = v0;
            *reinterpret_cast<float2*>(&C[(size_t)(r0 + 8) * ldc + c0]) = v1;
        }
    }
}

// Split-K reduction (deterministic order).
__global__ void reduce_kernel(const float* __restrict__ part, float* __restrict__ out,
                              int MN, int splits)
{
    int i = (blockIdx.x * blockDim.x + threadIdx.x) * 4;
    if (i >= MN) return;
    float4 s = *reinterpret_cast<const float4*>(&part[i]);
    for (int z = 1; z < splits; z++) {
        float4 t = *reinterpret_cast<const float4*>(&part[(size_t)z * MN + i]);
        s.x += t.x; s.y += t.y; s.z += t.z; s.w += t.w;
    }
    *reinterpret_cast<float4*>(&out[i]) = s;
}

// Split-K reduce + de-interleave: part [z][4096][256] -> out [8192][128]
__global__ void reduce_deint_kernel(const float* __restrict__ part, float* __restrict__ out,
                                    int splits)
{
    int o = (blockIdx.x * blockDim.x + threadIdx.x) * 4;   // over 8192*128
    int r = o >> 7;
    int c = o & 127;
    size_t src = (size_t)(r & 4095) * 256 + ((r >> 12) << 7) + c;
    const int MN = 4096 * 256;
    float4 s = *reinterpret_cast<const float4*>(&part[src]);
    for (int z = 1; z < splits; z++) {
        float4 t = *reinterpret_cast<const float4*>(&part[(size_t)z * MN + src]);
        s.x += t.x; s.y += t.y; s.z += t.z; s.w += t.w;
    }
    *reinterpret_cast<float4*>(&out[o]) = s;
}

// Pack [Xs | Xt] -> out [4096][256]
__global__ void pack_kernel(const float* __restrict__ Xs, const float* __restrict__ Xt,
                            float* __restrict__ out)
{
    int o = (blockIdx.x * blockDim.x + threadIdx.x) * 4;   // over 4096*256
    int r = o >> 8;
    int c = o & 255;
    float4 v = (c < 128)
        ? *reinterpret_cast<const float4*>(&Xs[(size_t)r * 128 + c])
        : *reinterpret_cast<const float4*>(&Xt[(size_t)r * 128 + (c - 128)]);
    *reinterpret_cast<float4*>(&out[o]) = v;
}

// ---------------------------------------------------------------------------
// Launch helpers
// ---------------------------------------------------------------------------
template <bool TB>
static void mma_launch(const float* A, const float* B, float* C,
                       int M, int N, int K, int lda, int ldb, int ldc,
                       int splits, int epi)
{
    cudaFuncSetAttribute(mma_gemm<TB>, cudaFuncAttributeMaxDynamicSharedMemorySize,
                         SMEM_BYTES);
    dim3 grid(N / 128, M / 128, splits);
    mma_gemm<TB><<<grid, 512, SMEM_BYTES>>>(A, B, C, M, N, K, lda, ldb, ldc,
                                            K / splits, epi);
}

static void reduce_launch(const float* part, float* out, int MN, int splits)
{
    reduce_kernel<<<MN / (4 * 256), 256>>>(part, out, MN, splits);
}

// One GCN branch: Xout = relu((A @ relu((A@X)@W1)) @ W2)
static void gcn_branch(const float* A, const float* X,
                       const float* W1, const float* W2,
                       float* Xout, float* split, float* bufAX, float* bufH)
{
    mma_launch<false>(A, X, split, GN, DIN, GN, GN, DIN, DIN, 2, 0);
    reduce_launch(split, bufAX, GN * DIN, 2);
    mma_launch<false>(bufAX, W1, bufH, GN, DH, DIN, DIN, DH, DH, 1, 1);
    mma_launch<false>(A, bufH, split, GN, DH, GN, GN, DH, DH, 4, 0);
    reduce_launch(split, bufAX, GN * DH, 4);
    mma_launch<false>(bufAX, W2, Xout, GN, DH, DH, DH, DH, DH, 1, 1);
}

extern "C" void kernel_launch(void* const* d_in, const int* in_sizes, int n_in,
                              void* d_out, int out_size)
{
    const float* A_s = (const float*)d_in[0];
    const float* X_s = (const float*)d_in[1];
    const float* A_t = (const float*)d_in[2];
    const float* X_t = (const float*)d_in[3];
    const float* W1  = (const float*)d_in[4];
    const float* W2  = (const float*)d_in[5];
    const float* W3  = (const float*)d_in[6];
    const float* W4  = (const float*)d_in[7];

    float* out_st = (float*)d_out;                       // [8192, 128] = out_s|out_t
    float* S      = out_st + (size_t)2 * GN * DH;        // [4096, 4096]

    float *split, *bufAX, *bufH, *bXs, *bXt, *bQ, *bP;
    cudaGetSymbolAddress((void**)&split, g_split);
    cudaGetSymbolAddress((void**)&bufAX, g_bufAX);
    cudaGetSymbolAddress((void**)&bufH,  g_bufH);
    cudaGetSymbolAddress((void**)&bXs,   g_Xs);
    cudaGetSymbolAddress((void**)&bXt,   g_Xt);
    cudaGetSymbolAddress((void**)&bQ,    g_Q);
    cudaGetSymbolAddress((void**)&bP,    g_P);

    // GCN branches
    gcn_branch(A_s, X_s, W1, W2, bXs, split, bufAX, bufH);
    gcn_branch(A_t, X_t, W1, W2, bXt, split, bufAX, bufH);

    // Q = Xs @ W3
    mma_launch<false>(bXs, W3, bQ, GN, DH, DH, DH, DH, DH, 1, 0);

    // S = exp(Q @ Xt^T)  (written straight into output; FFMA fast_exp epilogue)
    mma_launch<true>(bQ, bXt, S, GN, GN, DH, DH, DH, GN, 1, 2);

    // XsXt = [Xs | Xt]  [4096, 256]  (reuse bufAX)
    pack_kernel<<<GN * 256 / (4 * 256), 256>>>(bXs, bXt, bufAX);

    // P_pair = S @ [Xs|Xt]  [4096,256], K=4096, split-K=4 (one pass over S)
    mma_launch<false>(S, bufAX, split, GN, 2 * DH, GN, GN, 2 * DH, 2 * DH, 4, 0);
    reduce_deint_kernel<<<8192 * 128 / (4 * 256), 256>>>(split, bP, 4);

    // [out_s; out_t] = [Ps; Pt] @ W4   (M = 8192, writes d_out directly)
    mma_launch<false>(bP, W4, out_st, 2 * GN, DH, DH, DH, DH, DH, 1, 0);
}